// round 2
// baseline (speedup 1.0000x reference)
#include <cuda_runtime.h>
#include <math.h>

#define B_  4
#define L_  2048
#define H_  2048
#define NH_ 16
#define HD_ 128
#define M_  (B_ * L_)      // 8192
#define N3_ (3 * H_)       // 6144

// ---------------- scratch (device globals: only legal scratch) ----------------
__device__ float g_qkv[(size_t)M_ * N3_];          // 201 MB
__device__ float g_Q[(size_t)B_ * NH_ * L_ * HD_]; // 67 MB
__device__ float g_K[(size_t)B_ * NH_ * L_ * HD_];
__device__ float g_V[(size_t)B_ * NH_ * L_ * HD_];
__device__ float g_Y[(size_t)M_ * H_];             // 67 MB

// ---------------- fp32 tiled GEMM: C = A[MxK] * W[KxN] + bias, opt SiLU -------
// BM=BN=64, BK=16, 256 threads, each thread 4x4 (cols mapped tx+16*j for
// conflict-free smem reads and coalesced global writes).
__global__ void gemm_bias(const float* __restrict__ A, const float* __restrict__ W,
                          const float* __restrict__ bias, float* __restrict__ C,
                          int M, int N, int K, int act)
{
    __shared__ float As[16][65];
    __shared__ float Bs[16][65];
    const int tid = threadIdx.x;
    const int tx = tid & 15, ty = tid >> 4;
    const int row0 = blockIdx.y * 64, col0 = blockIdx.x * 64;

    float acc[4][4];
#pragma unroll
    for (int i = 0; i < 4; i++)
#pragma unroll
        for (int j = 0; j < 4; j++) acc[i][j] = 0.f;

    for (int k0 = 0; k0 < K; k0 += 16) {
#pragma unroll
        for (int i = tid; i < 1024; i += 256) {
            int m = i >> 4, k = i & 15;
            As[k][m] = A[(size_t)(row0 + m) * K + (k0 + k)];
        }
#pragma unroll
        for (int i = tid; i < 1024; i += 256) {
            int k = i >> 6, n = i & 63;
            Bs[k][n] = W[(size_t)(k0 + k) * N + (col0 + n)];
        }
        __syncthreads();
#pragma unroll
        for (int k = 0; k < 16; k++) {
            float a[4], b[4];
#pragma unroll
            for (int i = 0; i < 4; i++) a[i] = As[k][ty * 4 + i];
#pragma unroll
            for (int j = 0; j < 4; j++) b[j] = Bs[k][tx + 16 * j];
#pragma unroll
            for (int i = 0; i < 4; i++)
#pragma unroll
                for (int j = 0; j < 4; j++)
                    acc[i][j] = fmaf(a[i], b[j], acc[i][j]);
        }
        __syncthreads();
    }

#pragma unroll
    for (int i = 0; i < 4; i++) {
        int r = row0 + ty * 4 + i;
#pragma unroll
        for (int j = 0; j < 4; j++) {
            int c = col0 + tx + 16 * j;
            float v = acc[i][j] + bias[c];
            if (act) v = v / (1.0f + expf(-v));   // SiLU
            C[(size_t)r * N + c] = v;
        }
    }
}

// ---------------- RoPE + scatter to head-major [b,h,t,d] ----------------------
// Reference quirk: to_heads = reshape(b,l,HD,NH) -> head h, dim d is flat
// index e = d*16 + h. RoPE pairs (j, j+1024) over the full 2048-wide vector.
// For e1 = d*16+h with d<64: partner e2 = e1+1024 = (d+64)*16+h.
__global__ void rope_scatter(const float* __restrict__ qkv,
                             const float* __restrict__ cosb,
                             const float* __restrict__ sinb,
                             float* __restrict__ Q, float* __restrict__ K,
                             float* __restrict__ V)
{
    __shared__ float sh[N3_];
    const int bt = blockIdx.x;            // 0..8191
    const int b = bt >> 11, t = bt & 2047;
    const float* row = qkv + (size_t)bt * N3_;
    for (int i = threadIdx.x; i < N3_; i += blockDim.x) sh[i] = row[i];
    __syncthreads();

    // q and k (rotary)
    for (int i = threadIdx.x; i < 1024; i += blockDim.x) {
        int h = i >> 6;        // 0..15
        int d = i & 63;        // 0..63
        int e1 = d * 16 + h;   // < 1024
        float c = cosb[(size_t)t * 1024 + e1];
        float s = sinb[(size_t)t * 1024 + e1];
        size_t base = (((size_t)b * NH_ + h) * L_ + t) * HD_;

        float u1 = sh[e1], u2 = sh[e1 + 1024];
        Q[base + d]      =  u1 * c + u2 * s;
        Q[base + d + 64] = -u1 * s + u2 * c;

        u1 = sh[H_ + e1]; u2 = sh[H_ + e1 + 1024];
        K[base + d]      =  u1 * c + u2 * s;
        K[base + d + 64] = -u1 * s + u2 * c;
    }
    // v (no rotary)
    for (int i = threadIdx.x; i < H_; i += blockDim.x) {
        int h = i >> 7, d = i & 127;
        V[(((size_t)b * NH_ + h) * L_ + t) * HD_ + d] = sh[2 * H_ + d * 16 + h];
    }
}

// ---------------- flash attention (causal), BQ=BK=64 --------------------------
#define LDQ 129
#define ATTN_SMEM ((3 * 64 * LDQ + 64 * 64) * (int)sizeof(float))

__global__ void attn(const float* __restrict__ Q, const float* __restrict__ K,
                     const float* __restrict__ V, float* __restrict__ Y)
{
    extern __shared__ float smem[];
    float* sQ = smem;                 // 64 x 128, padded LDQ
    float* sK = sQ + 64 * LDQ;
    float* sV = sK + 64 * LDQ;
    float* sS = sV + 64 * LDQ;        // 64 x 64
    __shared__ float sm[64], sl[64], sa[64];

    const int tid = threadIdx.x;      // 256
    const int tx = tid & 15, ty = tid >> 4;
    const int qt = blockIdx.x;        // 0..31 query tile
    const int bh = blockIdx.y;        // 0..63 (b*16 + h)
    const float scale = 0.08838834764831843f;   // 1/sqrt(128)

    const float* Qb = Q + (size_t)bh * L_ * HD_ + (size_t)qt * 64 * HD_;
    const float* Kb = K + (size_t)bh * L_ * HD_;
    const float* Vb = V + (size_t)bh * L_ * HD_;

    for (int i = tid; i < 64 * 128; i += 256) {
        int r = i >> 7, c = i & 127;
        sQ[r * LDQ + c] = Qb[i];
    }
    if (tid < 64) { sm[tid] = -1e30f; sl[tid] = 0.f; }

    float acc[4][8];
#pragma unroll
    for (int i = 0; i < 4; i++)
#pragma unroll
        for (int j = 0; j < 8; j++) acc[i][j] = 0.f;
    __syncthreads();

    for (int kt = 0; kt <= qt; kt++) {
        for (int i = tid; i < 64 * 128; i += 256) {
            int r = i >> 7, c = i & 127;
            sK[r * LDQ + c] = Kb[(size_t)kt * 64 * HD_ + i];
            sV[r * LDQ + c] = Vb[(size_t)kt * 64 * HD_ + i];
        }
        __syncthreads();

        // S = Q K^T (4 rows x 4 cols per thread; cols tx+16*j conflict-free)
        float sacc[4][4];
#pragma unroll
        for (int i = 0; i < 4; i++)
#pragma unroll
            for (int j = 0; j < 4; j++) sacc[i][j] = 0.f;

        for (int kk = 0; kk < 128; kk++) {
            float a[4], b[4];
#pragma unroll
            for (int i = 0; i < 4; i++) a[i] = sQ[(ty * 4 + i) * LDQ + kk];
#pragma unroll
            for (int j = 0; j < 4; j++) b[j] = sK[(tx + 16 * j) * LDQ + kk];
#pragma unroll
            for (int i = 0; i < 4; i++)
#pragma unroll
                for (int j = 0; j < 4; j++)
                    sacc[i][j] = fmaf(a[i], b[j], sacc[i][j]);
        }

        const bool diag = (kt == qt);
#pragma unroll
        for (int i = 0; i < 4; i++) {
            int r = ty * 4 + i;
#pragma unroll
            for (int j = 0; j < 4; j++) {
                int c = tx + 16 * j;
                float v = sacc[i][j] * scale;
                if (diag && (kt * 64 + c > qt * 64 + r)) v = -1e30f;
                sS[r * 64 + c] = v;
            }
        }
        __syncthreads();

        // online softmax bookkeeping (one thread per row)
        if (tid < 64) {
            int r = tid;
            float mold = sm[r], mx = mold;
            for (int c = 0; c < 64; c++) mx = fmaxf(mx, sS[r * 64 + c]);
            float al = __expf(mold - mx);
            float sum = 0.f;
            for (int c = 0; c < 64; c++) {
                float p = __expf(sS[r * 64 + c] - mx);
                sS[r * 64 + c] = p;
                sum += p;
            }
            sm[r] = mx; sa[r] = al;
            sl[r] = sl[r] * al + sum;
        }
        __syncthreads();

        float al[4];
#pragma unroll
        for (int i = 0; i < 4; i++) al[i] = sa[ty * 4 + i];
#pragma unroll
        for (int i = 0; i < 4; i++)
#pragma unroll
            for (int j = 0; j < 8; j++) acc[i][j] *= al[i];

        // acc += P(64x64) * V(64x128)
        for (int kk = 0; kk < 64; kk++) {
            float p[4], v[8];
#pragma unroll
            for (int i = 0; i < 4; i++) p[i] = sS[(ty * 4 + i) * 64 + kk];
#pragma unroll
            for (int j = 0; j < 8; j++) v[j] = sV[kk * LDQ + tx + 16 * j];
#pragma unroll
            for (int i = 0; i < 4; i++)
#pragma unroll
                for (int j = 0; j < 8; j++)
                    acc[i][j] = fmaf(p[i], v[j], acc[i][j]);
        }
        __syncthreads();
    }

    // normalize + write y in [b, t, h*128 + d] layout
    const int b = bh >> 4, h = bh & 15;
    float li[4];
#pragma unroll
    for (int i = 0; i < 4; i++) li[i] = 1.0f / sl[ty * 4 + i];
#pragma unroll
    for (int i = 0; i < 4; i++) {
        int t = qt * 64 + ty * 4 + i;
#pragma unroll
        for (int j = 0; j < 8; j++) {
            int d = tx + 16 * j;
            g_Y[((size_t)(b * L_ + t)) * H_ + h * HD_ + d] = acc[i][j] * li[i];
        }
    }
}

// ---------------- launcher ----------------------------------------------------
extern "C" void kernel_launch(void* const* d_in, const int* in_sizes, int n_in,
                              void* d_out, int out_size)
{
    const float* x    = (const float*)d_in[0];
    const float* Wqkv = (const float*)d_in[1];
    const float* bqkv = (const float*)d_in[2];
    const float* Wfc2 = (const float*)d_in[3];
    const float* bfc2 = (const float*)d_in[4];
    const float* cosb = (const float*)d_in[5];
    const float* sinb = (const float*)d_in[6];
    float* out = (float*)d_out;

    float *qkv, *Qh, *Kh, *Vh, *Yb;
    cudaGetSymbolAddress((void**)&qkv, g_qkv);
    cudaGetSymbolAddress((void**)&Qh,  g_Q);
    cudaGetSymbolAddress((void**)&Kh,  g_K);
    cudaGetSymbolAddress((void**)&Vh,  g_V);
    cudaGetSymbolAddress((void**)&Yb,  g_Y);

    // 1) QKV GEMM: [8192 x 2048] @ [2048 x 6144] + bias
    gemm_bias<<<dim3(N3_ / 64, M_ / 64), 256>>>(x, Wqkv, bqkv, qkv, M_, N3_, H_, 0);

    // 2) RoPE + scatter to head-major
    rope_scatter<<<M_, 256>>>(qkv, cosb, sinb, Qh, Kh, Vh);

    // 3) causal flash attention
    cudaFuncSetAttribute(attn, cudaFuncAttributeMaxDynamicSharedMemorySize, ATTN_SMEM);
    attn<<<dim3(L_ / 64, B_ * NH_), 256, ATTN_SMEM>>>(Qh, Kh, Vh, Yb);

    // 4) FC2 GEMM + SiLU: [8192 x 2048] @ [2048 x 2048]
    gemm_bias<<<dim3(H_ / 64, M_ / 64), 256>>>(Yb, Wfc2, bfc2, out, M_, H_, H_, 1);
}

// round 3
// speedup vs baseline: 2.0548x; 2.0548x over previous
#include <cuda_runtime.h>
#include <math.h>
#include <stdint.h>

#define B_  4
#define L_  2048
#define H_  2048
#define NH_ 16
#define HD_ 128
#define M_  (B_ * L_)      // 8192
#define N3_ (3 * H_)       // 6144

// ---------------- scratch (device globals: only legal scratch) ----------------
__device__ float g_qkv[(size_t)M_ * N3_];          // 201 MB
__device__ float g_Q[(size_t)B_ * NH_ * L_ * HD_]; // 67 MB
__device__ float g_K[(size_t)B_ * NH_ * L_ * HD_];
__device__ float g_V[(size_t)B_ * NH_ * L_ * HD_];
__device__ float g_Y[(size_t)M_ * H_];             // 67 MB

// ================= tf32 tensor-core GEMM =====================================
// C[MxN] = A[MxK] @ W[KxN] + bias, optional SiLU.
// CTA tile 256x128, BK=32, 8 warps (4 m x 2 n), warp tile 64x64.
// mma.sync.m16n8k8 tf32, cp.async double buffering.
#define BM   256
#define BN   128
#define BKK  32
#define ASTR 36                      // words per A smem row (32 + 4 pad)
#define BSTR 132                     // words per B smem row (128 + 4 pad)
#define AWORDS (BM * ASTR)           // 9216
#define BWORDS (BKK * BSTR)          // 4224
#define GEMM_SMEM ((2 * AWORDS + 2 * BWORDS) * (int)sizeof(float))  // 107520 B

__device__ __forceinline__ uint32_t f2tf32(float x) {
    uint32_t r;
    asm("cvt.rna.tf32.f32 %0, %1;" : "=r"(r) : "f"(x));
    return r;
}

__device__ __forceinline__ void mma_tf32(float c[4], const uint32_t a[4], const uint32_t b[2]) {
    asm volatile(
        "mma.sync.aligned.m16n8k8.row.col.f32.tf32.tf32.f32 "
        "{%0,%1,%2,%3}, {%4,%5,%6,%7}, {%8,%9}, {%0,%1,%2,%3};\n"
        : "+f"(c[0]), "+f"(c[1]), "+f"(c[2]), "+f"(c[3])
        : "r"(a[0]), "r"(a[1]), "r"(a[2]), "r"(a[3]), "r"(b[0]), "r"(b[1]));
}

__global__ __launch_bounds__(256) void gemm_tf32(
    const float* __restrict__ A, const float* __restrict__ W,
    const float* __restrict__ bias, float* __restrict__ C,
    int M, int N, int K, int act)
{
    extern __shared__ float smem[];
    float* sA[2] = { smem, smem + AWORDS };
    float* sB[2] = { smem + 2 * AWORDS, smem + 2 * AWORDS + BWORDS };

    const int tid  = threadIdx.x;
    const int wid  = tid >> 5, lane = tid & 31;
    const int g    = lane >> 2, tg = lane & 3;
    const int wm   = (wid & 3) * 64;     // warp m offset
    const int wn   = (wid >> 2) * 64;    // warp n offset
    const int row0 = blockIdx.y * BM, col0 = blockIdx.x * BN;

    float acc[4][8][4];
#pragma unroll
    for (int i = 0; i < 4; i++)
#pragma unroll
        for (int j = 0; j < 8; j++)
#pragma unroll
            for (int r = 0; r < 4; r++) acc[i][j][r] = 0.f;

    auto loadTile = [&](int buf, int k0) {
        uint32_t sa = (uint32_t)__cvta_generic_to_shared(sA[buf]);
#pragma unroll
        for (int t = 0; t < 8; t++) {          // A: 256 rows x 8 chunks of 16B
            int idx = t * 256 + tid;
            int r = idx >> 3, c = idx & 7;
            const float* src = A + (size_t)(row0 + r) * K + k0 + c * 4;
            uint32_t dst = sa + (uint32_t)(r * ASTR + c * 4) * 4u;
            asm volatile("cp.async.cg.shared.global [%0], [%1], 16;\n" :: "r"(dst), "l"(src));
        }
        uint32_t sb = (uint32_t)__cvta_generic_to_shared(sB[buf]);
#pragma unroll
        for (int t = 0; t < 4; t++) {          // B: 32 rows x 32 chunks of 16B
            int idx = t * 256 + tid;
            int r = idx >> 5, c = idx & 31;
            const float* src = W + (size_t)(k0 + r) * N + col0 + c * 4;
            uint32_t dst = sb + (uint32_t)(r * BSTR + c * 4) * 4u;
            asm volatile("cp.async.cg.shared.global [%0], [%1], 16;\n" :: "r"(dst), "l"(src));
        }
    };

    auto compute = [&](int buf) {
        const float* sa = sA[buf];
        const float* sb = sB[buf];
#pragma unroll
        for (int kc = 0; kc < 4; kc++) {
            uint32_t af[4][4], bf[8][2];
            const int cA = kc * 8 + tg;
#pragma unroll
            for (int i = 0; i < 4; i++) {
                int rb = wm + i * 16;
                af[i][0] = f2tf32(sa[(rb + g) * ASTR + cA]);
                af[i][1] = f2tf32(sa[(rb + g + 8) * ASTR + cA]);
                af[i][2] = f2tf32(sa[(rb + g) * ASTR + cA + 4]);
                af[i][3] = f2tf32(sa[(rb + g + 8) * ASTR + cA + 4]);
            }
#pragma unroll
            for (int j = 0; j < 8; j++) {
                int cb = wn + j * 8 + g;
                bf[j][0] = f2tf32(sb[(kc * 8 + tg) * BSTR + cb]);
                bf[j][1] = f2tf32(sb[(kc * 8 + tg + 4) * BSTR + cb]);
            }
#pragma unroll
            for (int i = 0; i < 4; i++)
#pragma unroll
                for (int j = 0; j < 8; j++)
                    mma_tf32(acc[i][j], af[i], bf[j]);
        }
    };

    const int nIter = K / BKK;
    loadTile(0, 0);
    asm volatile("cp.async.commit_group;\n");
    for (int it = 0; it < nIter; it++) {
        asm volatile("cp.async.wait_group 0;\n");
        __syncthreads();
        if (it + 1 < nIter) {
            loadTile((it + 1) & 1, (it + 1) * BKK);
            asm volatile("cp.async.commit_group;\n");
        }
        compute(it & 1);
    }

    // epilogue: bias (+SiLU), float2 stores
#pragma unroll
    for (int i = 0; i < 4; i++) {
        int r = row0 + wm + i * 16 + g;
#pragma unroll
        for (int j = 0; j < 8; j++) {
            int c = col0 + wn + j * 8 + tg * 2;
            float b0 = bias[c], b1 = bias[c + 1];
            float v0 = acc[i][j][0] + b0;
            float v1 = acc[i][j][1] + b1;
            float v2 = acc[i][j][2] + b0;
            float v3 = acc[i][j][3] + b1;
            if (act) {
                v0 = v0 / (1.0f + expf(-v0));
                v1 = v1 / (1.0f + expf(-v1));
                v2 = v2 / (1.0f + expf(-v2));
                v3 = v3 / (1.0f + expf(-v3));
            }
            float2 p0 = make_float2(v0, v1);
            float2 p1 = make_float2(v2, v3);
            *(float2*)&C[(size_t)r * N + c] = p0;
            *(float2*)&C[(size_t)(r + 8) * N + c] = p1;
        }
    }
}

// ---------------- RoPE + scatter to head-major [b,h,t,d] ----------------------
__global__ void rope_scatter(const float* __restrict__ qkv,
                             const float* __restrict__ cosb,
                             const float* __restrict__ sinb,
                             float* __restrict__ Q, float* __restrict__ K,
                             float* __restrict__ V)
{
    __shared__ float sh[N3_];
    const int bt = blockIdx.x;
    const int b = bt >> 11, t = bt & 2047;
    const float* row = qkv + (size_t)bt * N3_;
    for (int i = threadIdx.x; i < N3_; i += blockDim.x) sh[i] = row[i];
    __syncthreads();

    for (int i = threadIdx.x; i < 1024; i += blockDim.x) {
        int h = i >> 6;
        int d = i & 63;
        int e1 = d * 16 + h;
        float c = cosb[(size_t)t * 1024 + e1];
        float s = sinb[(size_t)t * 1024 + e1];
        size_t base = (((size_t)b * NH_ + h) * L_ + t) * HD_;

        float u1 = sh[e1], u2 = sh[e1 + 1024];
        Q[base + d]      =  u1 * c + u2 * s;
        Q[base + d + 64] = -u1 * s + u2 * c;

        u1 = sh[H_ + e1]; u2 = sh[H_ + e1 + 1024];
        K[base + d]      =  u1 * c + u2 * s;
        K[base + d + 64] = -u1 * s + u2 * c;
    }
    for (int i = threadIdx.x; i < H_; i += blockDim.x) {
        int h = i >> 7, d = i & 127;
        V[(((size_t)b * NH_ + h) * L_ + t) * HD_ + d] = sh[2 * H_ + d * 16 + h];
    }
}

// ---------------- flash attention (causal), BQ=BK=64 --------------------------
#define LDQ 129
#define ATTN_SMEM ((3 * 64 * LDQ + 64 * 64) * (int)sizeof(float))

__global__ void attn(const float* __restrict__ Q, const float* __restrict__ K,
                     const float* __restrict__ V, float* __restrict__ Y)
{
    extern __shared__ float smem[];
    float* sQ = smem;
    float* sK = sQ + 64 * LDQ;
    float* sV = sK + 64 * LDQ;
    float* sS = sV + 64 * LDQ;
    __shared__ float sm[64], sl[64], sa[64];

    const int tid = threadIdx.x;
    const int tx = tid & 15, ty = tid >> 4;
    const int qt = blockIdx.x;
    const int bh = blockIdx.y;
    const float scale = 0.08838834764831843f;

    const float* Qb = Q + (size_t)bh * L_ * HD_ + (size_t)qt * 64 * HD_;
    const float* Kb = K + (size_t)bh * L_ * HD_;
    const float* Vb = V + (size_t)bh * L_ * HD_;

    for (int i = tid; i < 64 * 128; i += 256) {
        int r = i >> 7, c = i & 127;
        sQ[r * LDQ + c] = Qb[i];
    }
    if (tid < 64) { sm[tid] = -1e30f; sl[tid] = 0.f; }

    float acc[4][8];
#pragma unroll
    for (int i = 0; i < 4; i++)
#pragma unroll
        for (int j = 0; j < 8; j++) acc[i][j] = 0.f;
    __syncthreads();

    for (int kt = 0; kt <= qt; kt++) {
        for (int i = tid; i < 64 * 128; i += 256) {
            int r = i >> 7, c = i & 127;
            sK[r * LDQ + c] = Kb[(size_t)kt * 64 * HD_ + i];
            sV[r * LDQ + c] = Vb[(size_t)kt * 64 * HD_ + i];
        }
        __syncthreads();

        float sacc[4][4];
#pragma unroll
        for (int i = 0; i < 4; i++)
#pragma unroll
            for (int j = 0; j < 4; j++) sacc[i][j] = 0.f;

        for (int kk = 0; kk < 128; kk++) {
            float a[4], b[4];
#pragma unroll
            for (int i = 0; i < 4; i++) a[i] = sQ[(ty * 4 + i) * LDQ + kk];
#pragma unroll
            for (int j = 0; j < 4; j++) b[j] = sK[(tx + 16 * j) * LDQ + kk];
#pragma unroll
            for (int i = 0; i < 4; i++)
#pragma unroll
                for (int j = 0; j < 4; j++)
                    sacc[i][j] = fmaf(a[i], b[j], sacc[i][j]);
        }

        const bool diag = (kt == qt);
#pragma unroll
        for (int i = 0; i < 4; i++) {
            int r = ty * 4 + i;
#pragma unroll
            for (int j = 0; j < 4; j++) {
                int c = tx + 16 * j;
                float v = sacc[i][j] * scale;
                if (diag && (kt * 64 + c > qt * 64 + r)) v = -1e30f;
                sS[r * 64 + c] = v;
            }
        }
        __syncthreads();

        if (tid < 64) {
            int r = tid;
            float mold = sm[r], mx = mold;
            for (int c = 0; c < 64; c++) mx = fmaxf(mx, sS[r * 64 + c]);
            float al = __expf(mold - mx);
            float sum = 0.f;
            for (int c = 0; c < 64; c++) {
                float p = __expf(sS[r * 64 + c] - mx);
                sS[r * 64 + c] = p;
                sum += p;
            }
            sm[r] = mx; sa[r] = al;
            sl[r] = sl[r] * al + sum;
        }
        __syncthreads();

        float al[4];
#pragma unroll
        for (int i = 0; i < 4; i++) al[i] = sa[ty * 4 + i];
#pragma unroll
        for (int i = 0; i < 4; i++)
#pragma unroll
            for (int j = 0; j < 8; j++) acc[i][j] *= al[i];

        for (int kk = 0; kk < 64; kk++) {
            float p[4], v[8];
#pragma unroll
            for (int i = 0; i < 4; i++) p[i] = sS[(ty * 4 + i) * 64 + kk];
#pragma unroll
            for (int j = 0; j < 8; j++) v[j] = sV[kk * LDQ + tx + 16 * j];
#pragma unroll
            for (int i = 0; i < 4; i++)
#pragma unroll
                for (int j = 0; j < 8; j++)
                    acc[i][j] = fmaf(p[i], v[j], acc[i][j]);
        }
        __syncthreads();
    }

    const int b = bh >> 4, h = bh & 15;
    float li[4];
#pragma unroll
    for (int i = 0; i < 4; i++) li[i] = 1.0f / sl[ty * 4 + i];
#pragma unroll
    for (int i = 0; i < 4; i++) {
        int t = qt * 64 + ty * 4 + i;
#pragma unroll
        for (int j = 0; j < 8; j++) {
            int d = tx + 16 * j;
            g_Y[((size_t)(b * L_ + t)) * H_ + h * HD_ + d] = acc[i][j] * li[i];
        }
    }
}

// ---------------- launcher ----------------------------------------------------
extern "C" void kernel_launch(void* const* d_in, const int* in_sizes, int n_in,
                              void* d_out, int out_size)
{
    const float* x    = (const float*)d_in[0];
    const float* Wqkv = (const float*)d_in[1];
    const float* bqkv = (const float*)d_in[2];
    const float* Wfc2 = (const float*)d_in[3];
    const float* bfc2 = (const float*)d_in[4];
    const float* cosb = (const float*)d_in[5];
    const float* sinb = (const float*)d_in[6];
    float* out = (float*)d_out;

    float *qkv, *Qh, *Kh, *Vh, *Yb;
    cudaGetSymbolAddress((void**)&qkv, g_qkv);
    cudaGetSymbolAddress((void**)&Qh,  g_Q);
    cudaGetSymbolAddress((void**)&Kh,  g_K);
    cudaGetSymbolAddress((void**)&Vh,  g_V);
    cudaGetSymbolAddress((void**)&Yb,  g_Y);

    cudaFuncSetAttribute(gemm_tf32, cudaFuncAttributeMaxDynamicSharedMemorySize, GEMM_SMEM);
    cudaFuncSetAttribute(attn, cudaFuncAttributeMaxDynamicSharedMemorySize, ATTN_SMEM);

    // 1) QKV GEMM: [8192 x 2048] @ [2048 x 6144] + bias
    gemm_tf32<<<dim3(N3_ / BN, M_ / BM), 256, GEMM_SMEM>>>(x, Wqkv, bqkv, qkv, M_, N3_, H_, 0);

    // 2) RoPE + scatter to head-major
    rope_scatter<<<M_, 256>>>(qkv, cosb, sinb, Qh, Kh, Vh);

    // 3) causal flash attention
    attn<<<dim3(L_ / 64, B_ * NH_), 256, ATTN_SMEM>>>(Qh, Kh, Vh, Yb);

    // 4) FC2 GEMM + SiLU: [8192 x 2048] @ [2048 x 2048]
    gemm_tf32<<<dim3(H_ / BN, M_ / BM), 256, GEMM_SMEM>>>(Yb, Wfc2, bfc2, out, M_, H_, H_, 1);
}

// round 4
// speedup vs baseline: 5.1279x; 2.4956x over previous
#include <cuda_runtime.h>
#include <math.h>
#include <stdint.h>

#define B_  4
#define L_  2048
#define H_  2048
#define NH_ 16
#define HD_ 128
#define M_  (B_ * L_)      // 8192
#define N3_ (3 * H_)       // 6144

// ---------------- scratch (device globals: only legal scratch) ----------------
__device__ float g_qkv[(size_t)M_ * N3_];          // 201 MB
__device__ float g_Q[(size_t)B_ * NH_ * L_ * HD_]; // 67 MB
__device__ float g_K[(size_t)B_ * NH_ * L_ * HD_];
__device__ float g_V[(size_t)B_ * NH_ * L_ * HD_];
__device__ float g_Y[(size_t)M_ * H_];             // 67 MB

__device__ __forceinline__ uint32_t f2tf32(float x) {
    uint32_t r;
    asm("cvt.rna.tf32.f32 %0, %1;" : "=r"(r) : "f"(x));
    return r;
}

__device__ __forceinline__ void mma_tf32(float c[4], const uint32_t a[4], const uint32_t b[2]) {
    asm volatile(
        "mma.sync.aligned.m16n8k8.row.col.f32.tf32.tf32.f32 "
        "{%0,%1,%2,%3}, {%4,%5,%6,%7}, {%8,%9}, {%0,%1,%2,%3};\n"
        : "+f"(c[0]), "+f"(c[1]), "+f"(c[2]), "+f"(c[3])
        : "r"(a[0]), "r"(a[1]), "r"(a[2]), "r"(a[3]), "r"(b[0]), "r"(b[1]));
}

// ================= tf32 tensor-core GEMM =====================================
#define BM   256
#define BN   128
#define BKK  32
#define ASTR 36
#define BSTR 132
#define AWORDS (BM * ASTR)
#define BWORDS (BKK * BSTR)
#define GEMM_SMEM ((2 * AWORDS + 2 * BWORDS) * (int)sizeof(float))

__global__ __launch_bounds__(256) void gemm_tf32(
    const float* __restrict__ A, const float* __restrict__ W,
    const float* __restrict__ bias, float* __restrict__ C,
    int M, int N, int K, int act)
{
    extern __shared__ float smem[];
    float* sA[2] = { smem, smem + AWORDS };
    float* sB[2] = { smem + 2 * AWORDS, smem + 2 * AWORDS + BWORDS };

    const int tid  = threadIdx.x;
    const int wid  = tid >> 5, lane = tid & 31;
    const int g    = lane >> 2, tg = lane & 3;
    const int wm   = (wid & 3) * 64;
    const int wn   = (wid >> 2) * 64;
    const int row0 = blockIdx.y * BM, col0 = blockIdx.x * BN;

    float acc[4][8][4];
#pragma unroll
    for (int i = 0; i < 4; i++)
#pragma unroll
        for (int j = 0; j < 8; j++)
#pragma unroll
            for (int r = 0; r < 4; r++) acc[i][j][r] = 0.f;

    auto loadTile = [&](int buf, int k0) {
        uint32_t sa = (uint32_t)__cvta_generic_to_shared(sA[buf]);
#pragma unroll
        for (int t = 0; t < 8; t++) {
            int idx = t * 256 + tid;
            int r = idx >> 3, c = idx & 7;
            const float* src = A + (size_t)(row0 + r) * K + k0 + c * 4;
            uint32_t dst = sa + (uint32_t)(r * ASTR + c * 4) * 4u;
            asm volatile("cp.async.cg.shared.global [%0], [%1], 16;\n" :: "r"(dst), "l"(src));
        }
        uint32_t sb = (uint32_t)__cvta_generic_to_shared(sB[buf]);
#pragma unroll
        for (int t = 0; t < 4; t++) {
            int idx = t * 256 + tid;
            int r = idx >> 5, c = idx & 31;
            const float* src = W + (size_t)(k0 + r) * N + col0 + c * 4;
            uint32_t dst = sb + (uint32_t)(r * BSTR + c * 4) * 4u;
            asm volatile("cp.async.cg.shared.global [%0], [%1], 16;\n" :: "r"(dst), "l"(src));
        }
    };

    auto compute = [&](int buf) {
        const float* sa = sA[buf];
        const float* sb = sB[buf];
#pragma unroll
        for (int kc = 0; kc < 4; kc++) {
            uint32_t af[4][4], bf[8][2];
            const int cA = kc * 8 + tg;
#pragma unroll
            for (int i = 0; i < 4; i++) {
                int rb = wm + i * 16;
                af[i][0] = f2tf32(sa[(rb + g) * ASTR + cA]);
                af[i][1] = f2tf32(sa[(rb + g + 8) * ASTR + cA]);
                af[i][2] = f2tf32(sa[(rb + g) * ASTR + cA + 4]);
                af[i][3] = f2tf32(sa[(rb + g + 8) * ASTR + cA + 4]);
            }
#pragma unroll
            for (int j = 0; j < 8; j++) {
                int cb = wn + j * 8 + g;
                bf[j][0] = f2tf32(sb[(kc * 8 + tg) * BSTR + cb]);
                bf[j][1] = f2tf32(sb[(kc * 8 + tg + 4) * BSTR + cb]);
            }
#pragma unroll
            for (int i = 0; i < 4; i++)
#pragma unroll
                for (int j = 0; j < 8; j++)
                    mma_tf32(acc[i][j], af[i], bf[j]);
        }
    };

    const int nIter = K / BKK;
    loadTile(0, 0);
    asm volatile("cp.async.commit_group;\n");
    for (int it = 0; it < nIter; it++) {
        asm volatile("cp.async.wait_group 0;\n");
        __syncthreads();
        if (it + 1 < nIter) {
            loadTile((it + 1) & 1, (it + 1) * BKK);
            asm volatile("cp.async.commit_group;\n");
        }
        compute(it & 1);
    }

#pragma unroll
    for (int i = 0; i < 4; i++) {
        int r = row0 + wm + i * 16 + g;
#pragma unroll
        for (int j = 0; j < 8; j++) {
            int c = col0 + wn + j * 8 + tg * 2;
            float b0 = bias[c], b1 = bias[c + 1];
            float v0 = acc[i][j][0] + b0;
            float v1 = acc[i][j][1] + b1;
            float v2 = acc[i][j][2] + b0;
            float v3 = acc[i][j][3] + b1;
            if (act) {
                v0 = v0 / (1.0f + expf(-v0));
                v1 = v1 / (1.0f + expf(-v1));
                v2 = v2 / (1.0f + expf(-v2));
                v3 = v3 / (1.0f + expf(-v3));
            }
            *(float2*)&C[(size_t)r * N + c] = make_float2(v0, v1);
            *(float2*)&C[(size_t)(r + 8) * N + c] = make_float2(v2, v3);
        }
    }
}

// ---------------- RoPE + scatter to head-major [b,h,t,d] ----------------------
__global__ void rope_scatter(const float* __restrict__ qkv,
                             const float* __restrict__ cosb,
                             const float* __restrict__ sinb,
                             float* __restrict__ Q, float* __restrict__ K,
                             float* __restrict__ V)
{
    __shared__ float sh[N3_];
    const int bt = blockIdx.x;
    const int b = bt >> 11, t = bt & 2047;
    const float* row = qkv + (size_t)bt * N3_;
    for (int i = threadIdx.x; i < N3_; i += blockDim.x) sh[i] = row[i];
    __syncthreads();

    for (int i = threadIdx.x; i < 1024; i += blockDim.x) {
        int h = i >> 6;
        int d = i & 63;
        int e1 = d * 16 + h;
        float c = cosb[(size_t)t * 1024 + e1];
        float s = sinb[(size_t)t * 1024 + e1];
        size_t base = (((size_t)b * NH_ + h) * L_ + t) * HD_;

        float u1 = sh[e1], u2 = sh[e1 + 1024];
        Q[base + d]      =  u1 * c + u2 * s;
        Q[base + d + 64] = -u1 * s + u2 * c;

        u1 = sh[H_ + e1]; u2 = sh[H_ + e1 + 1024];
        K[base + d]      =  u1 * c + u2 * s;
        K[base + d + 64] = -u1 * s + u2 * c;
    }
    for (int i = threadIdx.x; i < H_; i += blockDim.x) {
        int h = i >> 7, d = i & 127;
        V[(((size_t)b * NH_ + h) * L_ + t) * HD_ + d] = sh[2 * H_ + d * 16 + h];
    }
}

// ================= tensor-core flash attention (causal) ======================
// BQ=BK=64, HD=128, 8 warps: warp grid 4(m) x 2(n).
// S warp-tile 16x32, O warp-tile 16x64 (held in regs across KV tiles).
// smem strides: Q/K 132, V 136, S 68 -> all fragment LDS bank-conflict-free.
#define LDQK 132
#define LDV  136
#define LDS_ 68
#define ATTN_SMEM ((3 * 64 * LDQK + 2 * 64 * LDV + 64 * LDS_) * (int)sizeof(float))

__global__ __launch_bounds__(256) void attn_tc(
    const float* __restrict__ Q, const float* __restrict__ K,
    const float* __restrict__ V, float* __restrict__ Y)
{
    extern __shared__ float smem[];
    float* sQ  = smem;                    // 64 x 132
    float* sKb[2] = { sQ + 64 * LDQK, sQ + 2 * 64 * LDQK };
    float* sVb[2] = { sQ + 3 * 64 * LDQK, sQ + 3 * 64 * LDQK + 64 * LDV };
    float* sS  = sQ + 3 * 64 * LDQK + 2 * 64 * LDV;   // 64 x 68
    __shared__ float sm_[64], sl_[64], sa_[64];

    const int tid  = threadIdx.x;
    const int wid  = tid >> 5, lane = tid & 31;
    const int g    = lane >> 2, tg = lane & 3;
    const int wm   = (wid & 3) * 16;     // S/O row offset
    const int wnS  = (wid >> 2) * 32;    // S col offset
    const int wnO  = (wid >> 2) * 64;    // O dim offset
    const int qt   = blockIdx.x;         // query tile 0..31
    const int bh   = blockIdx.y;         // b*16+h
    const float scale = 0.08838834764831843f;

    const float* Qg = Q + (size_t)bh * L_ * HD_ + (size_t)qt * 64 * HD_;
    const float* Kg = K + (size_t)bh * L_ * HD_;
    const float* Vg = V + (size_t)bh * L_ * HD_;

    // Q tile via cp.async
    {
        uint32_t sq = (uint32_t)__cvta_generic_to_shared(sQ);
#pragma unroll
        for (int t = 0; t < 8; t++) {
            int idx = t * 256 + tid;
            int r = idx >> 5, c = idx & 31;
            const float* src = Qg + r * HD_ + c * 4;
            uint32_t dst = sq + (uint32_t)(r * LDQK + c * 4) * 4u;
            asm volatile("cp.async.cg.shared.global [%0], [%1], 16;\n" :: "r"(dst), "l"(src));
        }
    }
    if (tid < 64) { sm_[tid] = -1e30f; sl_[tid] = 0.f; }

    auto loadKV = [&](int buf, int kt2) {
        const float* Kp = Kg + (size_t)kt2 * 64 * HD_;
        const float* Vp = Vg + (size_t)kt2 * 64 * HD_;
        uint32_t sk = (uint32_t)__cvta_generic_to_shared(sKb[buf]);
        uint32_t sv = (uint32_t)__cvta_generic_to_shared(sVb[buf]);
#pragma unroll
        for (int t = 0; t < 8; t++) {
            int idx = t * 256 + tid;
            int r = idx >> 5, c = idx & 31;
            uint32_t dk = sk + (uint32_t)(r * LDQK + c * 4) * 4u;
            asm volatile("cp.async.cg.shared.global [%0], [%1], 16;\n" :: "r"(dk), "l"(Kp + r * HD_ + c * 4));
        }
#pragma unroll
        for (int t = 0; t < 8; t++) {
            int idx = t * 256 + tid;
            int r = idx >> 5, c = idx & 31;
            uint32_t dv = sv + (uint32_t)(r * LDV + c * 4) * 4u;
            asm volatile("cp.async.cg.shared.global [%0], [%1], 16;\n" :: "r"(dv), "l"(Vp + r * HD_ + c * 4));
        }
    };

    float o[8][4];
#pragma unroll
    for (int j = 0; j < 8; j++)
#pragma unroll
        for (int r = 0; r < 4; r++) o[j][r] = 0.f;

    loadKV(0, 0);
    asm volatile("cp.async.commit_group;\n");   // group: Q + K/V tile 0

    for (int kt = 0; kt <= qt; kt++) {
        const int buf = kt & 1;
        if (kt < qt) {
            loadKV(buf ^ 1, kt + 1);
            asm volatile("cp.async.commit_group;\n");
            asm volatile("cp.async.wait_group 1;\n");
        } else {
            asm volatile("cp.async.wait_group 0;\n");
        }
        __syncthreads();

        const float* sK_ = sKb[buf];
        const float* sV_ = sVb[buf];

        // ---- S = Q K^T (warp tile 16x32) ----
        float sacc[4][4];
#pragma unroll
        for (int n = 0; n < 4; n++)
#pragma unroll
            for (int r = 0; r < 4; r++) sacc[n][r] = 0.f;

#pragma unroll
        for (int kc = 0; kc < 16; kc++) {
            const int ka = kc * 8 + tg;
            uint32_t af[4];
            af[0] = f2tf32(sQ[(wm + g) * LDQK + ka]);
            af[1] = f2tf32(sQ[(wm + g + 8) * LDQK + ka]);
            af[2] = f2tf32(sQ[(wm + g) * LDQK + ka + 4]);
            af[3] = f2tf32(sQ[(wm + g + 8) * LDQK + ka + 4]);
#pragma unroll
            for (int n = 0; n < 4; n++) {
                uint32_t bf[2];
                const int kr = wnS + n * 8 + g;
                bf[0] = f2tf32(sK_[kr * LDQK + ka]);
                bf[1] = f2tf32(sK_[kr * LDQK + ka + 4]);
                mma_tf32(sacc[n], af, bf);
            }
        }

        // ---- write S to smem with scale + causal mask ----
        const bool diag = (kt == qt);
#pragma unroll
        for (int n = 0; n < 4; n++) {
            int c0 = wnS + n * 8 + tg * 2;
            int r0 = wm + g, r1 = wm + g + 8;
            float v0 = sacc[n][0] * scale;
            float v1 = sacc[n][1] * scale;
            float v2 = sacc[n][2] * scale;
            float v3 = sacc[n][3] * scale;
            if (diag) {
                if (c0 > r0)     v0 = -1e30f;
                if (c0 + 1 > r0) v1 = -1e30f;
                if (c0 > r1)     v2 = -1e30f;
                if (c0 + 1 > r1) v3 = -1e30f;
            }
            *(float2*)&sS[r0 * LDS_ + c0] = make_float2(v0, v1);
            *(float2*)&sS[r1 * LDS_ + c0] = make_float2(v2, v3);
        }
        __syncthreads();

        // ---- parallel online softmax: 4 lanes per row ----
        {
            const int r = tid >> 2, q = tid & 3;
            float* rowp = sS + r * LDS_ + q * 16;
            float mx = -1e30f;
#pragma unroll
            for (int j = 0; j < 16; j++) mx = fmaxf(mx, rowp[j]);
            mx = fmaxf(mx, __shfl_xor_sync(0xffffffffu, mx, 1));
            mx = fmaxf(mx, __shfl_xor_sync(0xffffffffu, mx, 2));
            const float mold = sm_[r];
            const float mnew = fmaxf(mold, mx);
            float sum = 0.f;
#pragma unroll
            for (int j = 0; j < 16; j++) {
                float p = __expf(rowp[j] - mnew);
                rowp[j] = p;
                sum += p;
            }
            sum += __shfl_xor_sync(0xffffffffu, sum, 1);
            sum += __shfl_xor_sync(0xffffffffu, sum, 2);
            if (q == 0) {
                float al = __expf(mold - mnew);
                sa_[r] = al;
                sm_[r] = mnew;
                sl_[r] = sl_[r] * al + sum;
            }
        }
        __syncthreads();

        // ---- rescale O, then O += P V ----
        {
            float a0 = sa_[wm + g], a1 = sa_[wm + g + 8];
#pragma unroll
            for (int n = 0; n < 8; n++) {
                o[n][0] *= a0; o[n][1] *= a0;
                o[n][2] *= a1; o[n][3] *= a1;
            }
        }
#pragma unroll
        for (int kc = 0; kc < 8; kc++) {
            const int ka = kc * 8 + tg;
            uint32_t af[4];
            af[0] = f2tf32(sS[(wm + g) * LDS_ + ka]);
            af[1] = f2tf32(sS[(wm + g + 8) * LDS_ + ka]);
            af[2] = f2tf32(sS[(wm + g) * LDS_ + ka + 4]);
            af[3] = f2tf32(sS[(wm + g + 8) * LDS_ + ka + 4]);
#pragma unroll
            for (int n = 0; n < 8; n++) {
                uint32_t bf[2];
                const int dn = wnO + n * 8 + g;
                bf[0] = f2tf32(sV_[ka * LDV + dn]);
                bf[1] = f2tf32(sV_[(ka + 4) * LDV + dn]);
                mma_tf32(o[n], af, bf);
            }
        }
        __syncthreads();   // protect sS and KV buffers for next iteration
    }

    // ---- epilogue: normalize + write y[b, t, h*128+d] ----
    const int b = bh >> 4, h = bh & 15;
    const float inv0 = 1.0f / sl_[wm + g];
    const float inv1 = 1.0f / sl_[wm + g + 8];
    const int t0 = qt * 64 + wm + g;
    const int t1 = t0 + 8;
#pragma unroll
    for (int n = 0; n < 8; n++) {
        int d = wnO + n * 8 + tg * 2;
        *(float2*)&Y[((size_t)(b * L_ + t0)) * H_ + h * HD_ + d] =
            make_float2(o[n][0] * inv0, o[n][1] * inv0);
        *(float2*)&Y[((size_t)(b * L_ + t1)) * H_ + h * HD_ + d] =
            make_float2(o[n][2] * inv1, o[n][3] * inv1);
    }
}

// ---------------- launcher ----------------------------------------------------
extern "C" void kernel_launch(void* const* d_in, const int* in_sizes, int n_in,
                              void* d_out, int out_size)
{
    const float* x    = (const float*)d_in[0];
    const float* Wqkv = (const float*)d_in[1];
    const float* bqkv = (const float*)d_in[2];
    const float* Wfc2 = (const float*)d_in[3];
    const float* bfc2 = (const float*)d_in[4];
    const float* cosb = (const float*)d_in[5];
    const float* sinb = (const float*)d_in[6];
    float* out = (float*)d_out;

    float *qkv, *Qh, *Kh, *Vh, *Yb;
    cudaGetSymbolAddress((void**)&qkv, g_qkv);
    cudaGetSymbolAddress((void**)&Qh,  g_Q);
    cudaGetSymbolAddress((void**)&Kh,  g_K);
    cudaGetSymbolAddress((void**)&Vh,  g_V);
    cudaGetSymbolAddress((void**)&Yb,  g_Y);

    cudaFuncSetAttribute(gemm_tf32, cudaFuncAttributeMaxDynamicSharedMemorySize, GEMM_SMEM);
    cudaFuncSetAttribute(attn_tc, cudaFuncAttributeMaxDynamicSharedMemorySize, ATTN_SMEM);

    // 1) QKV GEMM
    gemm_tf32<<<dim3(N3_ / BN, M_ / BM), 256, GEMM_SMEM>>>(x, Wqkv, bqkv, qkv, M_, N3_, H_, 0);

    // 2) RoPE + scatter
    rope_scatter<<<M_, 256>>>(qkv, cosb, sinb, Qh, Kh, Vh);

    // 3) tensor-core causal flash attention
    attn_tc<<<dim3(L_ / 64, B_ * NH_), 256, ATTN_SMEM>>>(Qh, Kh, Vh, Yb);

    // 4) FC2 GEMM + SiLU
    gemm_tf32<<<dim3(H_ / BN, M_ / BM), 256, GEMM_SMEM>>>(Yb, Wfc2, bfc2, out, M_, H_, H_, 1);
}

// round 7
// speedup vs baseline: 5.5882x; 1.0898x over previous
#include <cuda_runtime.h>
#include <math.h>
#include <stdint.h>

#define B_  4
#define L_  2048
#define H_  2048
#define NH_ 16
#define HD_ 128
#define M_  (B_ * L_)      // 8192
#define N3_ (3 * H_)       // 6144

// ---------------- scratch (device globals: only legal scratch) ----------------
__device__ float g_qkv[(size_t)M_ * N3_];
__device__ float g_Q[(size_t)B_ * NH_ * L_ * HD_];
__device__ float g_K[(size_t)B_ * NH_ * L_ * HD_];
__device__ float g_V[(size_t)B_ * NH_ * L_ * HD_];
__device__ float g_Y[(size_t)M_ * H_];

__device__ __forceinline__ uint32_t f2tf32(float x) {
    uint32_t r;
    asm("cvt.rna.tf32.f32 %0, %1;" : "=r"(r) : "f"(x));
    return r;
}
__device__ __forceinline__ float rnd_tf32(float x) {
    return __uint_as_float(f2tf32(x));
}

__device__ __forceinline__ void mma_tf32(float c[4], const uint32_t a[4], const uint32_t b[2]) {
    asm volatile(
        "mma.sync.aligned.m16n8k8.row.col.f32.tf32.tf32.f32 "
        "{%0,%1,%2,%3}, {%4,%5,%6,%7}, {%8,%9}, {%0,%1,%2,%3};\n"
        : "+f"(c[0]), "+f"(c[1]), "+f"(c[2]), "+f"(c[3])
        : "r"(a[0]), "r"(a[1]), "r"(a[2]), "r"(a[3]), "r"(b[0]), "r"(b[1]));
}

// ================= tf32 tensor-core GEMM (unchanged, at mma.sync peak) =======
#define BM   256
#define BN   128
#define BKK  32
#define ASTR 36
#define BSTR 132
#define AWORDS (BM * ASTR)
#define BWORDS (BKK * BSTR)
#define GEMM_SMEM ((2 * AWORDS + 2 * BWORDS) * (int)sizeof(float))

__global__ __launch_bounds__(256) void gemm_tf32(
    const float* __restrict__ A, const float* __restrict__ W,
    const float* __restrict__ bias, float* __restrict__ C,
    int M, int N, int K, int act)
{
    extern __shared__ float smem[];
    float* sA[2] = { smem, smem + AWORDS };
    float* sB[2] = { smem + 2 * AWORDS, smem + 2 * AWORDS + BWORDS };

    const int tid  = threadIdx.x;
    const int wid  = tid >> 5, lane = tid & 31;
    const int g    = lane >> 2, tg = lane & 3;
    const int wm   = (wid & 3) * 64;
    const int wn   = (wid >> 2) * 64;
    const int row0 = blockIdx.y * BM, col0 = blockIdx.x * BN;

    float acc[4][8][4];
#pragma unroll
    for (int i = 0; i < 4; i++)
#pragma unroll
        for (int j = 0; j < 8; j++)
#pragma unroll
            for (int r = 0; r < 4; r++) acc[i][j][r] = 0.f;

    auto loadTile = [&](int buf, int k0) {
        uint32_t sa = (uint32_t)__cvta_generic_to_shared(sA[buf]);
#pragma unroll
        for (int t = 0; t < 8; t++) {
            int idx = t * 256 + tid;
            int r = idx >> 3, c = idx & 7;
            const float* src = A + (size_t)(row0 + r) * K + k0 + c * 4;
            uint32_t dst = sa + (uint32_t)(r * ASTR + c * 4) * 4u;
            asm volatile("cp.async.cg.shared.global [%0], [%1], 16;\n" :: "r"(dst), "l"(src));
        }
        uint32_t sb = (uint32_t)__cvta_generic_to_shared(sB[buf]);
#pragma unroll
        for (int t = 0; t < 4; t++) {
            int idx = t * 256 + tid;
            int r = idx >> 5, c = idx & 31;
            const float* src = W + (size_t)(k0 + r) * N + col0 + c * 4;
            uint32_t dst = sb + (uint32_t)(r * BSTR + c * 4) * 4u;
            asm volatile("cp.async.cg.shared.global [%0], [%1], 16;\n" :: "r"(dst), "l"(src));
        }
    };

    auto compute = [&](int buf) {
        const float* sa = sA[buf];
        const float* sb = sB[buf];
#pragma unroll
        for (int kc = 0; kc < 4; kc++) {
            uint32_t af[4][4], bf[8][2];
            const int cA = kc * 8 + tg;
#pragma unroll
            for (int i = 0; i < 4; i++) {
                int rb = wm + i * 16;
                af[i][0] = f2tf32(sa[(rb + g) * ASTR + cA]);
                af[i][1] = f2tf32(sa[(rb + g + 8) * ASTR + cA]);
                af[i][2] = f2tf32(sa[(rb + g) * ASTR + cA + 4]);
                af[i][3] = f2tf32(sa[(rb + g + 8) * ASTR + cA + 4]);
            }
#pragma unroll
            for (int j = 0; j < 8; j++) {
                int cb = wn + j * 8 + g;
                bf[j][0] = f2tf32(sb[(kc * 8 + tg) * BSTR + cb]);
                bf[j][1] = f2tf32(sb[(kc * 8 + tg + 4) * BSTR + cb]);
            }
#pragma unroll
            for (int i = 0; i < 4; i++)
#pragma unroll
                for (int j = 0; j < 8; j++)
                    mma_tf32(acc[i][j], af[i], bf[j]);
        }
    };

    const int nIter = K / BKK;
    loadTile(0, 0);
    asm volatile("cp.async.commit_group;\n");
    for (int it = 0; it < nIter; it++) {
        asm volatile("cp.async.wait_group 0;\n");
        __syncthreads();
        if (it + 1 < nIter) {
            loadTile((it + 1) & 1, (it + 1) * BKK);
            asm volatile("cp.async.commit_group;\n");
        }
        compute(it & 1);
    }

#pragma unroll
    for (int i = 0; i < 4; i++) {
        int r = row0 + wm + i * 16 + g;
#pragma unroll
        for (int j = 0; j < 8; j++) {
            int c = col0 + wn + j * 8 + tg * 2;
            float b0 = bias[c], b1 = bias[c + 1];
            float v0 = acc[i][j][0] + b0;
            float v1 = acc[i][j][1] + b1;
            float v2 = acc[i][j][2] + b0;
            float v3 = acc[i][j][3] + b1;
            if (act) {
                v0 = v0 / (1.0f + expf(-v0));
                v1 = v1 / (1.0f + expf(-v1));
                v2 = v2 / (1.0f + expf(-v2));
                v3 = v3 / (1.0f + expf(-v3));
            }
            *(float2*)&C[(size_t)r * N + c] = make_float2(v0, v1);
            *(float2*)&C[(size_t)(r + 8) * N + c] = make_float2(v2, v3);
        }
    }
}

// ---------------- RoPE + scatter; outputs PRE-ROUNDED to tf32 -----------------
// Q additionally pre-scaled by 1/sqrt(HD) so attention needs no scale/cvt.
__global__ void rope_scatter(const float* __restrict__ qkv,
                             const float* __restrict__ cosb,
                             const float* __restrict__ sinb,
                             float* __restrict__ Q, float* __restrict__ K,
                             float* __restrict__ V)
{
    __shared__ float sh[N3_];
    const int bt = blockIdx.x;
    const int b = bt >> 11, t = bt & 2047;
    const float scale = 0.08838834764831843f;   // 1/sqrt(128)
    const float* row = qkv + (size_t)bt * N3_;
    for (int i = threadIdx.x; i < N3_; i += blockDim.x) sh[i] = row[i];
    __syncthreads();

    for (int i = threadIdx.x; i < 1024; i += blockDim.x) {
        int h = i >> 6;
        int d = i & 63;
        int e1 = d * 16 + h;
        float c = cosb[(size_t)t * 1024 + e1];
        float s = sinb[(size_t)t * 1024 + e1];
        size_t base = (((size_t)b * NH_ + h) * L_ + t) * HD_;

        float u1 = sh[e1], u2 = sh[e1 + 1024];
        Q[base + d]      = rnd_tf32(( u1 * c + u2 * s) * scale);
        Q[base + d + 64] = rnd_tf32((-u1 * s + u2 * c) * scale);

        u1 = sh[H_ + e1]; u2 = sh[H_ + e1 + 1024];
        K[base + d]      = rnd_tf32( u1 * c + u2 * s);
        K[base + d + 64] = rnd_tf32(-u1 * s + u2 * c);
    }
    for (int i = threadIdx.x; i < H_; i += blockDim.x) {
        int h = i >> 7, d = i & 127;
        V[(((size_t)b * NH_ + h) * L_ + t) * HD_ + d] = rnd_tf32(sh[2 * H_ + d * 16 + h]);
    }
}

// ================= flash attention v2: BQ=128, warp-local softmax =============
// 8 warps; warp w owns rows [16w,16w+16) across the FULL 64-col K tile.
// Q resident in smem (stride 132). K stride 132, V stride 136: all fragment
// LDS patterns are exact lane permutations (conflict-free).
#define LDQK 132
#define LDV  136
#define ATTN_SMEM ((128 * LDQK + 2 * 64 * LDQK + 2 * 64 * LDV) * (int)sizeof(float)) // 204800

__global__ __launch_bounds__(256, 1) void attn_tc2(
    const float* __restrict__ Q, const float* __restrict__ K,
    const float* __restrict__ V, float* __restrict__ Y)
{
    extern __shared__ float smem[];
    float* sQ = smem;                               // 128 x 132
    float* sKb[2] = { sQ + 128 * LDQK, sQ + 128 * LDQK + 64 * LDQK };
    float* sVb[2] = { sQ + 128 * LDQK + 2 * 64 * LDQK,
                      sQ + 128 * LDQK + 2 * 64 * LDQK + 64 * LDV };

    const int tid  = threadIdx.x;
    const int wid  = tid >> 5, lane = tid & 31;
    const int g    = lane >> 2, tg = lane & 3;
    const int wm   = wid * 16;
    const int qt   = 15 - (int)blockIdx.x;          // descending work size
    const int bh   = blockIdx.y;

    const float* Qg = Q + (size_t)bh * L_ * HD_ + (size_t)qt * 128 * HD_;
    const float* Kg = K + (size_t)bh * L_ * HD_;
    const float* Vg = V + (size_t)bh * L_ * HD_;

    // ---- load Q tile (once) ----
    {
        uint32_t sq = (uint32_t)__cvta_generic_to_shared(sQ);
#pragma unroll
        for (int t = 0; t < 16; t++) {
            int idx = t * 256 + tid;
            int r = idx >> 5, c = idx & 31;
            uint32_t dst = sq + (uint32_t)(r * LDQK + c * 4) * 4u;
            asm volatile("cp.async.cg.shared.global [%0], [%1], 16;\n"
                         :: "r"(dst), "l"(Qg + r * HD_ + c * 4));
        }
    }

    auto loadKV = [&](int buf, int kt2) {
        const float* Kp = Kg + (size_t)kt2 * 64 * HD_;
        const float* Vp = Vg + (size_t)kt2 * 64 * HD_;
        uint32_t sk = (uint32_t)__cvta_generic_to_shared(sKb[buf]);
        uint32_t sv = (uint32_t)__cvta_generic_to_shared(sVb[buf]);
#pragma unroll
        for (int t = 0; t < 8; t++) {
            int idx = t * 256 + tid;
            int r = idx >> 5, c = idx & 31;
            uint32_t dk = sk + (uint32_t)(r * LDQK + c * 4) * 4u;
            asm volatile("cp.async.cg.shared.global [%0], [%1], 16;\n"
                         :: "r"(dk), "l"(Kp + r * HD_ + c * 4));
        }
#pragma unroll
        for (int t = 0; t < 8; t++) {
            int idx = t * 256 + tid;
            int r = idx >> 5, c = idx & 31;
            uint32_t dv = sv + (uint32_t)(r * LDV + c * 4) * 4u;
            asm volatile("cp.async.cg.shared.global [%0], [%1], 16;\n"
                         :: "r"(dv), "l"(Vp + r * HD_ + c * 4));
        }
    };

    float of[16][4];
#pragma unroll
    for (int n = 0; n < 16; n++)
#pragma unroll
        for (int r = 0; r < 4; r++) of[n][r] = 0.f;
    float m0 = -1e30f, m1 = -1e30f, l0 = 0.f, l1 = 0.f;

    const int nt = 2 * qt + 2;
    asm volatile("cp.async.commit_group;\n");       // Q group
    loadKV(0, 0);
    asm volatile("cp.async.commit_group;\n");

    for (int kt = 0; kt < nt; kt++) {
        const int buf = kt & 1;
        if (kt + 1 < nt) {
            loadKV(buf ^ 1, kt + 1);
            asm volatile("cp.async.commit_group;\n");
            asm volatile("cp.async.wait_group 1;\n");
        } else {
            asm volatile("cp.async.wait_group 0;\n");
        }
        __syncthreads();

        const int rowmin = qt * 128 + wm;
        const bool fullM = (kt * 64 > rowmin + 15);   // warp fully masked
        if (!fullM) {
            const float* sK_ = sKb[buf];
            const float* sV_ = sVb[buf];

            // ---- S = Q K^T : warp tile 16x64 ----
            float sacc[8][4];
#pragma unroll
            for (int n = 0; n < 8; n++)
#pragma unroll
                for (int r = 0; r < 4; r++) sacc[n][r] = 0.f;

#pragma unroll
            for (int kc = 0; kc < 16; kc++) {
                const int ka = kc * 8 + tg;
                uint32_t af[4];
                af[0] = __float_as_uint(sQ[(wm + g) * LDQK + ka]);
                af[1] = __float_as_uint(sQ[(wm + g + 8) * LDQK + ka]);
                af[2] = __float_as_uint(sQ[(wm + g) * LDQK + ka + 4]);
                af[3] = __float_as_uint(sQ[(wm + g + 8) * LDQK + ka + 4]);
#pragma unroll
                for (int n = 0; n < 8; n++) {
                    uint32_t bf[2];
                    bf[0] = __float_as_uint(sK_[(8 * n + g) * LDQK + ka]);
                    bf[1] = __float_as_uint(sK_[(8 * n + g) * LDQK + ka + 4]);
                    mma_tf32(sacc[n], af, bf);
                }
            }

            // ---- causal mask (only possible on diagonal tiles) ----
            if (kt * 64 + 63 > rowmin) {
                const int r0 = rowmin + g, r1 = r0 + 8;
#pragma unroll
                for (int n = 0; n < 8; n++) {
                    int c0 = kt * 64 + 8 * n + 2 * tg;
                    if (c0 > r0)     sacc[n][0] = -1e30f;
                    if (c0 + 1 > r0) sacc[n][1] = -1e30f;
                    if (c0 > r1)     sacc[n][2] = -1e30f;
                    if (c0 + 1 > r1) sacc[n][3] = -1e30f;
                }
            }

            // ---- warp-local online softmax (quad reductions) ----
            float vx0 = -1e30f, vx1 = -1e30f;
#pragma unroll
            for (int n = 0; n < 8; n++) {
                vx0 = fmaxf(vx0, fmaxf(sacc[n][0], sacc[n][1]));
                vx1 = fmaxf(vx1, fmaxf(sacc[n][2], sacc[n][3]));
            }
            vx0 = fmaxf(vx0, __shfl_xor_sync(0xffffffffu, vx0, 1));
            vx0 = fmaxf(vx0, __shfl_xor_sync(0xffffffffu, vx0, 2));
            vx1 = fmaxf(vx1, __shfl_xor_sync(0xffffffffu, vx1, 1));
            vx1 = fmaxf(vx1, __shfl_xor_sync(0xffffffffu, vx1, 2));

            const float mn0 = fmaxf(m0, vx0), mn1 = fmaxf(m1, vx1);
            const float a0 = __expf(m0 - mn0), a1 = __expf(m1 - mn1);
            m0 = mn0; m1 = mn1;

            float s0 = 0.f, s1 = 0.f;
#pragma unroll
            for (int n = 0; n < 8; n++) {
                float p0 = __expf(sacc[n][0] - mn0);
                float p1 = __expf(sacc[n][1] - mn0);
                float p2 = __expf(sacc[n][2] - mn1);
                float p3 = __expf(sacc[n][3] - mn1);
                s0 += p0 + p1; s1 += p2 + p3;
                sacc[n][0] = __uint_as_float(f2tf32(p0));
                sacc[n][1] = __uint_as_float(f2tf32(p1));
                sacc[n][2] = __uint_as_float(f2tf32(p2));
                sacc[n][3] = __uint_as_float(f2tf32(p3));
            }
            s0 += __shfl_xor_sync(0xffffffffu, s0, 1);
            s0 += __shfl_xor_sync(0xffffffffu, s0, 2);
            s1 += __shfl_xor_sync(0xffffffffu, s1, 1);
            s1 += __shfl_xor_sync(0xffffffffu, s1, 2);
            l0 = l0 * a0 + s0;
            l1 = l1 * a1 + s1;

#pragma unroll
            for (int n = 0; n < 16; n++) {
                of[n][0] *= a0; of[n][1] *= a0;
                of[n][2] *= a1; of[n][3] *= a1;
            }

            // ---- O += P V : P fragments via quad shuffles ----
            const int base = lane & ~3;
            const int hsrc = base + (tg >> 1);
            const bool par = (tg & 1);
#pragma unroll
            for (int kc = 0; kc < 8; kc++) {
                uint32_t a[4];
                {
                    float lo = __shfl_sync(0xffffffffu, sacc[kc][0], hsrc);
                    float hi = __shfl_sync(0xffffffffu, sacc[kc][1], hsrc);
                    a[0] = __float_as_uint(par ? hi : lo);
                    lo = __shfl_sync(0xffffffffu, sacc[kc][2], hsrc);
                    hi = __shfl_sync(0xffffffffu, sacc[kc][3], hsrc);
                    a[1] = __float_as_uint(par ? hi : lo);
                    lo = __shfl_sync(0xffffffffu, sacc[kc][0], hsrc + 2);
                    hi = __shfl_sync(0xffffffffu, sacc[kc][1], hsrc + 2);
                    a[2] = __float_as_uint(par ? hi : lo);
                    lo = __shfl_sync(0xffffffffu, sacc[kc][2], hsrc + 2);
                    hi = __shfl_sync(0xffffffffu, sacc[kc][3], hsrc + 2);
                    a[3] = __float_as_uint(par ? hi : lo);
                }
                const int kr = 8 * kc + tg;
#pragma unroll
                for (int n = 0; n < 16; n++) {
                    uint32_t bf[2];
                    bf[0] = __float_as_uint(sV_[kr * LDV + 8 * n + g]);
                    bf[1] = __float_as_uint(sV_[(kr + 4) * LDV + 8 * n + g]);
                    mma_tf32(of[n], a, bf);
                }
            }
        }
        __syncthreads();
    }

    // ---- epilogue: normalize + write y[b, t, h*128+d] ----
    const int b = bh >> 4, h = bh & 15;
    const float inv0 = 1.0f / l0;
    const float inv1 = 1.0f / l1;
    const int t0 = qt * 128 + wm + g;
    const int t1 = t0 + 8;
#pragma unroll
    for (int n = 0; n < 16; n++) {
        int d = 8 * n + 2 * tg;
        *(float2*)&Y[((size_t)(b * L_ + t0)) * H_ + h * HD_ + d] =
            make_float2(of[n][0] * inv0, of[n][1] * inv0);
        *(float2*)&Y[((size_t)(b * L_ + t1)) * H_ + h * HD_ + d] =
            make_float2(of[n][2] * inv1, of[n][3] * inv1);
    }
}

// ---------------- launcher ----------------------------------------------------
extern "C" void kernel_launch(void* const* d_in, const int* in_sizes, int n_in,
                              void* d_out, int out_size)
{
    const float* x    = (const float*)d_in[0];
    const float* Wqkv = (const float*)d_in[1];
    const float* bqkv = (const float*)d_in[2];
    const float* Wfc2 = (const float*)d_in[3];
    const float* bfc2 = (const float*)d_in[4];
    const float* cosb = (const float*)d_in[5];
    const float* sinb = (const float*)d_in[6];
    float* out = (float*)d_out;

    float *qkv, *Qh, *Kh, *Vh, *Yb;
    cudaGetSymbolAddress((void**)&qkv, g_qkv);
    cudaGetSymbolAddress((void**)&Qh,  g_Q);
    cudaGetSymbolAddress((void**)&Kh,  g_K);
    cudaGetSymbolAddress((void**)&Vh,  g_V);
    cudaGetSymbolAddress((void**)&Yb,  g_Y);

    cudaFuncSetAttribute(gemm_tf32, cudaFuncAttributeMaxDynamicSharedMemorySize, GEMM_SMEM);
    cudaFuncSetAttribute(attn_tc2, cudaFuncAttributeMaxDynamicSharedMemorySize, ATTN_SMEM);

    // 1) QKV GEMM
    gemm_tf32<<<dim3(N3_ / BN, M_ / BM), 256, GEMM_SMEM>>>(x, Wqkv, bqkv, qkv, M_, N3_, H_, 0);

    // 2) RoPE + scatter (pre-rounded tf32, Q pre-scaled)
    rope_scatter<<<M_, 256>>>(qkv, cosb, sinb, Qh, Kh, Vh);

    // 3) causal flash attention v2
    attn_tc2<<<dim3(L_ / 128, B_ * NH_), 256, ATTN_SMEM>>>(Qh, Kh, Vh, Yb);

    // 4) FC2 GEMM + SiLU
    gemm_tf32<<<dim3(H_ / BN, M_ / BM), 256, GEMM_SMEM>>>(Yb, Wfc2, bfc2, out, M_, H_, H_, 1);
}

// round 8
// speedup vs baseline: 5.7626x; 1.0312x over previous
#include <cuda_runtime.h>
#include <math.h>
#include <stdint.h>

#define B_  4
#define L_  2048
#define H_  2048
#define NH_ 16
#define HD_ 128
#define M_  (B_ * L_)      // 8192
#define N3_ (3 * H_)       // 6144

// ---------------- scratch (device globals: only legal scratch) ----------------
__device__ float g_qkv[(size_t)M_ * N3_];
__device__ float g_Q[(size_t)B_ * NH_ * L_ * HD_];
// K,V stored in FRAGMENT-MAJOR blocks: [bh][32 tiles][8192 words]
__device__ float g_K[(size_t)B_ * NH_ * 32 * 8192];
__device__ float g_V[(size_t)B_ * NH_ * 32 * 8192];
__device__ float g_Y[(size_t)M_ * H_];

__device__ __forceinline__ uint32_t f2tf32(float x) {
    uint32_t r;
    asm("cvt.rna.tf32.f32 %0, %1;" : "=r"(r) : "f"(x));
    return r;
}
__device__ __forceinline__ float rnd_tf32(float x) {
    return __uint_as_float(f2tf32(x));
}

__device__ __forceinline__ void mma_tf32(float c[4], const uint32_t a[4], const uint32_t b[2]) {
    asm volatile(
        "mma.sync.aligned.m16n8k8.row.col.f32.tf32.tf32.f32 "
        "{%0,%1,%2,%3}, {%4,%5,%6,%7}, {%8,%9}, {%0,%1,%2,%3};\n"
        : "+f"(c[0]), "+f"(c[1]), "+f"(c[2]), "+f"(c[3])
        : "r"(a[0]), "r"(a[1]), "r"(a[2]), "r"(a[3]), "r"(b[0]), "r"(b[1]));
}

// ================= tf32 tensor-core GEMM (unchanged, at mma.sync peak) =======
#define BM   256
#define BN   128
#define BKK  32
#define ASTR 36
#define BSTR 132
#define AWORDS (BM * ASTR)
#define BWORDS (BKK * BSTR)
#define GEMM_SMEM ((2 * AWORDS + 2 * BWORDS) * (int)sizeof(float))

__global__ __launch_bounds__(256) void gemm_tf32(
    const float* __restrict__ A, const float* __restrict__ W,
    const float* __restrict__ bias, float* __restrict__ C,
    int M, int N, int K, int act)
{
    extern __shared__ float smem[];
    float* sA[2] = { smem, smem + AWORDS };
    float* sB[2] = { smem + 2 * AWORDS, smem + 2 * AWORDS + BWORDS };

    const int tid  = threadIdx.x;
    const int wid  = tid >> 5, lane = tid & 31;
    const int g    = lane >> 2, tg = lane & 3;
    const int wm   = (wid & 3) * 64;
    const int wn   = (wid >> 2) * 64;
    const int row0 = blockIdx.y * BM, col0 = blockIdx.x * BN;

    float acc[4][8][4];
#pragma unroll
    for (int i = 0; i < 4; i++)
#pragma unroll
        for (int j = 0; j < 8; j++)
#pragma unroll
            for (int r = 0; r < 4; r++) acc[i][j][r] = 0.f;

    auto loadTile = [&](int buf, int k0) {
        uint32_t sa = (uint32_t)__cvta_generic_to_shared(sA[buf]);
#pragma unroll
        for (int t = 0; t < 8; t++) {
            int idx = t * 256 + tid;
            int r = idx >> 3, c = idx & 7;
            const float* src = A + (size_t)(row0 + r) * K + k0 + c * 4;
            uint32_t dst = sa + (uint32_t)(r * ASTR + c * 4) * 4u;
            asm volatile("cp.async.cg.shared.global [%0], [%1], 16;\n" :: "r"(dst), "l"(src));
        }
        uint32_t sb = (uint32_t)__cvta_generic_to_shared(sB[buf]);
#pragma unroll
        for (int t = 0; t < 4; t++) {
            int idx = t * 256 + tid;
            int r = idx >> 5, c = idx & 31;
            const float* src = W + (size_t)(k0 + r) * N + col0 + c * 4;
            uint32_t dst = sb + (uint32_t)(r * BSTR + c * 4) * 4u;
            asm volatile("cp.async.cg.shared.global [%0], [%1], 16;\n" :: "r"(dst), "l"(src));
        }
    };

    auto compute = [&](int buf) {
        const float* sa = sA[buf];
        const float* sb = sB[buf];
#pragma unroll
        for (int kc = 0; kc < 4; kc++) {
            uint32_t af[4][4], bf[8][2];
            const int cA = kc * 8 + tg;
#pragma unroll
            for (int i = 0; i < 4; i++) {
                int rb = wm + i * 16;
                af[i][0] = f2tf32(sa[(rb + g) * ASTR + cA]);
                af[i][1] = f2tf32(sa[(rb + g + 8) * ASTR + cA]);
                af[i][2] = f2tf32(sa[(rb + g) * ASTR + cA + 4]);
                af[i][3] = f2tf32(sa[(rb + g + 8) * ASTR + cA + 4]);
            }
#pragma unroll
            for (int j = 0; j < 8; j++) {
                int cb = wn + j * 8 + g;
                bf[j][0] = f2tf32(sb[(kc * 8 + tg) * BSTR + cb]);
                bf[j][1] = f2tf32(sb[(kc * 8 + tg + 4) * BSTR + cb]);
            }
#pragma unroll
            for (int i = 0; i < 4; i++)
#pragma unroll
                for (int j = 0; j < 8; j++)
                    mma_tf32(acc[i][j], af[i], bf[j]);
        }
    };

    const int nIter = K / BKK;
    loadTile(0, 0);
    asm volatile("cp.async.commit_group;\n");
    for (int it = 0; it < nIter; it++) {
        asm volatile("cp.async.wait_group 0;\n");
        __syncthreads();
        if (it + 1 < nIter) {
            loadTile((it + 1) & 1, (it + 1) * BKK);
            asm volatile("cp.async.commit_group;\n");
        }
        compute(it & 1);
    }

#pragma unroll
    for (int i = 0; i < 4; i++) {
        int r = row0 + wm + i * 16 + g;
#pragma unroll
        for (int j = 0; j < 8; j++) {
            int c = col0 + wn + j * 8 + tg * 2;
            float b0 = bias[c], b1 = bias[c + 1];
            float v0 = acc[i][j][0] + b0;
            float v1 = acc[i][j][1] + b1;
            float v2 = acc[i][j][2] + b0;
            float v3 = acc[i][j][3] + b1;
            if (act) {
                v0 = v0 / (1.0f + expf(-v0));
                v1 = v1 / (1.0f + expf(-v1));
                v2 = v2 / (1.0f + expf(-v2));
                v3 = v3 / (1.0f + expf(-v3));
            }
            *(float2*)&C[(size_t)r * N + c] = make_float2(v0, v1);
            *(float2*)&C[(size_t)(r + 8) * N + c] = make_float2(v2, v3);
        }
    }
}

// ---------------- RoPE + scatter -----------------------------------------------
// Q: [bh][t][d] row-major, tf32-rounded, pre-scaled by 1/sqrt(HD).
// K, V: FRAGMENT-MAJOR per (bh, 64-row tile):
//   K word: ((n*16+kc)*32 + g*4+tg)*2 + dlt   for row r=8n+g, col d=8*kc+tg+4*dlt
//   V word: ((kc*16+n)*32 + tg*8+g)*2 + dlt   for row r=8*kc+tg+4*dlt, col d=8n+g
__global__ void rope_scatter(const float* __restrict__ qkv,
                             const float* __restrict__ cosb,
                             const float* __restrict__ sinb,
                             float* __restrict__ Q, float* __restrict__ K,
                             float* __restrict__ V)
{
    __shared__ float sh[N3_];
    const int bt = blockIdx.x;
    const int b = bt >> 11, t = bt & 2047;
    const float scale = 0.08838834764831843f;
    const float* row = qkv + (size_t)bt * N3_;
    for (int i = threadIdx.x; i < N3_; i += blockDim.x) sh[i] = row[i];
    __syncthreads();

    const int tile = t >> 6, r = t & 63;
    const int Kn = r >> 3, Kg = r & 7;              // K frag coords from row
    const int Vkc = r >> 3, Vtg = r & 3, Vdlt = (r >> 2) & 1;  // V frag coords

    for (int i = threadIdx.x; i < 1024; i += blockDim.x) {
        int h = i >> 6;
        int d = i & 63;                 // 0..63 ; pairs (d, d+64)
        int e1 = d * 16 + h;
        float c = cosb[(size_t)t * 1024 + e1];
        float s = sinb[(size_t)t * 1024 + e1];
        const int bh = b * NH_ + h;

        float u1 = sh[e1], u2 = sh[e1 + 1024];
        size_t qbase = ((size_t)bh * L_ + t) * HD_;
        Q[qbase + d]      = rnd_tf32(( u1 * c + u2 * s) * scale);
        Q[qbase + d + 64] = rnd_tf32((-u1 * s + u2 * c) * scale);

        u1 = sh[H_ + e1]; u2 = sh[H_ + e1 + 1024];
        float k0 = rnd_tf32( u1 * c + u2 * s);
        float k1 = rnd_tf32(-u1 * s + u2 * c);
        size_t kbase = ((size_t)bh * 32 + tile) * 8192;
        // dim d: kc=d>>3, tg=d&3, dlt=(d>>2)&1 ; dim d+64: kc+8, same tg/dlt
        int kc = d >> 3, tg = d & 3, dlt = (d >> 2) & 1;
        K[kbase + (size_t)(((Kn * 16 + kc) * 32 + Kg * 4 + tg) * 2 + dlt)]       = k0;
        K[kbase + (size_t)(((Kn * 16 + kc + 8) * 32 + Kg * 4 + tg) * 2 + dlt)]   = k1;
    }
    for (int i = threadIdx.x; i < H_; i += blockDim.x) {
        int h = i >> 7, dd = i & 127;
        int n = dd >> 3, g = dd & 7;
        size_t vbase = (((size_t)(b * NH_ + h)) * 32 + tile) * 8192;
        V[vbase + (size_t)(((Vkc * 16 + n) * 32 + Vtg * 8 + g) * 2 + Vdlt)] =
            rnd_tf32(sh[2 * H_ + dd * 16 + h]);
    }
}

// ================= flash attention v3 =========================================
// BQ=128, BK=64, 8 warps (16 rows each). Q fragments hoisted to registers.
// K/V tiles copied flat (fragment-major); all fragment reads are LDS.64.
#define QSTR 132
#define QWORDS (128 * QSTR)
#define ATTN_SMEM ((QWORDS + 4 * 8192) * (int)sizeof(float))   // 198656 B

__global__ __launch_bounds__(256, 1) void attn_tc3(
    const float* __restrict__ Q, const float* __restrict__ K,
    const float* __restrict__ V, float* __restrict__ Y)
{
    extern __shared__ float smem[];
    float* sQ = smem;                                   // 128 x 132 (staging)
    float* sKb[2] = { smem + QWORDS, smem + QWORDS + 8192 };
    float* sVb[2] = { smem + QWORDS + 2 * 8192, smem + QWORDS + 3 * 8192 };

    const int tid  = threadIdx.x;
    const int wid  = tid >> 5, lane = tid & 31;
    const int g    = lane >> 2, tg = lane & 3;
    const int wm   = wid * 16;
    const int qt   = 15 - (int)blockIdx.x;
    const int bh   = blockIdx.y;

    const float* Qg = Q + (size_t)bh * L_ * HD_ + (size_t)qt * 128 * HD_;
    const float* Kg = K + (size_t)bh * 32 * 8192;
    const float* Vg = V + (size_t)bh * 32 * 8192;

    auto loadKV = [&](int buf, int kt2) {
        const float* Kp = Kg + (size_t)kt2 * 8192;
        const float* Vp = Vg + (size_t)kt2 * 8192;
        uint32_t sk = (uint32_t)__cvta_generic_to_shared(sKb[buf]);
        uint32_t sv = (uint32_t)__cvta_generic_to_shared(sVb[buf]);
#pragma unroll
        for (int t = 0; t < 8; t++) {
            int w4 = (t * 256 + tid) * 4;
            asm volatile("cp.async.cg.shared.global [%0], [%1], 16;\n"
                         :: "r"(sk + (uint32_t)w4 * 4u), "l"(Kp + w4));
            asm volatile("cp.async.cg.shared.global [%0], [%1], 16;\n"
                         :: "r"(sv + (uint32_t)w4 * 4u), "l"(Vp + w4));
        }
    };

    // ---- stage Q + first KV tile ----
    {
        uint32_t sq = (uint32_t)__cvta_generic_to_shared(sQ);
#pragma unroll
        for (int t = 0; t < 16; t++) {
            int idx = t * 256 + tid;
            int r = idx >> 5, c = idx & 31;
            asm volatile("cp.async.cg.shared.global [%0], [%1], 16;\n"
                         :: "r"(sq + (uint32_t)(r * QSTR + c * 4) * 4u),
                            "l"(Qg + r * HD_ + c * 4));
        }
    }
    loadKV(0, 0);
    asm volatile("cp.async.commit_group;\n");
    asm volatile("cp.async.wait_group 0;\n");
    __syncthreads();

    // ---- hoist Q fragments to registers ----
    uint32_t qf[16][4];
#pragma unroll
    for (int kc = 0; kc < 16; kc++) {
        const int ka = kc * 8 + tg;
        qf[kc][0] = __float_as_uint(sQ[(wm + g) * QSTR + ka]);
        qf[kc][1] = __float_as_uint(sQ[(wm + g + 8) * QSTR + ka]);
        qf[kc][2] = __float_as_uint(sQ[(wm + g) * QSTR + ka + 4]);
        qf[kc][3] = __float_as_uint(sQ[(wm + g + 8) * QSTR + ka + 4]);
    }

    float of[16][4];
#pragma unroll
    for (int n = 0; n < 16; n++)
#pragma unroll
        for (int r = 0; r < 4; r++) of[n][r] = 0.f;
    float m0 = -1e30f, m1 = -1e30f, l0 = 0.f, l1 = 0.f;

    const int nt = 2 * qt + 2;

    for (int kt = 0; kt < nt; kt++) {
        const int buf = kt & 1;
        if (kt + 1 < nt) {
            loadKV(buf ^ 1, kt + 1);
            asm volatile("cp.async.commit_group;\n");
            asm volatile("cp.async.wait_group 1;\n");
        } else {
            asm volatile("cp.async.wait_group 0;\n");
        }
        __syncthreads();

        const int rowmin = qt * 128 + wm;
        const bool fullM = (kt * 64 > rowmin + 15);
        if (!fullM) {
            const float2* sK2 = (const float2*)sKb[buf];
            const float2* sV2 = (const float2*)sVb[buf];
            const int kOff = g * 4 + tg;
            const int vOff = tg * 8 + g;

            // ---- S = Q K^T : warp tile 16x64, LDS.64 K fragments ----
            float sacc[8][4];
#pragma unroll
            for (int n = 0; n < 8; n++)
#pragma unroll
                for (int r = 0; r < 4; r++) sacc[n][r] = 0.f;

#pragma unroll
            for (int kc = 0; kc < 16; kc++) {
#pragma unroll
                for (int n = 0; n < 8; n++) {
                    float2 kv = sK2[(n * 16 + kc) * 32 + kOff];
                    uint32_t bf[2] = { __float_as_uint(kv.x), __float_as_uint(kv.y) };
                    mma_tf32(sacc[n], qf[kc], bf);
                }
            }

            // ---- causal mask ----
            if (kt * 64 + 63 > rowmin) {
                const int r0 = rowmin + g, r1 = r0 + 8;
#pragma unroll
                for (int n = 0; n < 8; n++) {
                    int c0 = kt * 64 + 8 * n + 2 * tg;
                    if (c0 > r0)     sacc[n][0] = -1e30f;
                    if (c0 + 1 > r0) sacc[n][1] = -1e30f;
                    if (c0 > r1)     sacc[n][2] = -1e30f;
                    if (c0 + 1 > r1) sacc[n][3] = -1e30f;
                }
            }

            // ---- warp-local online softmax ----
            float vx0 = -1e30f, vx1 = -1e30f;
#pragma unroll
            for (int n = 0; n < 8; n++) {
                vx0 = fmaxf(vx0, fmaxf(sacc[n][0], sacc[n][1]));
                vx1 = fmaxf(vx1, fmaxf(sacc[n][2], sacc[n][3]));
            }
            vx0 = fmaxf(vx0, __shfl_xor_sync(0xffffffffu, vx0, 1));
            vx0 = fmaxf(vx0, __shfl_xor_sync(0xffffffffu, vx0, 2));
            vx1 = fmaxf(vx1, __shfl_xor_sync(0xffffffffu, vx1, 1));
            vx1 = fmaxf(vx1, __shfl_xor_sync(0xffffffffu, vx1, 2));

            const float mn0 = fmaxf(m0, vx0), mn1 = fmaxf(m1, vx1);
            const float a0 = __expf(m0 - mn0), a1 = __expf(m1 - mn1);
            m0 = mn0; m1 = mn1;

            float s0 = 0.f, s1 = 0.f;
#pragma unroll
            for (int n = 0; n < 8; n++) {
                float p0 = __expf(sacc[n][0] - mn0);
                float p1 = __expf(sacc[n][1] - mn0);
                float p2 = __expf(sacc[n][2] - mn1);
                float p3 = __expf(sacc[n][3] - mn1);
                s0 += p0 + p1; s1 += p2 + p3;
                sacc[n][0] = __uint_as_float(f2tf32(p0));
                sacc[n][1] = __uint_as_float(f2tf32(p1));
                sacc[n][2] = __uint_as_float(f2tf32(p2));
                sacc[n][3] = __uint_as_float(f2tf32(p3));
            }
            s0 += __shfl_xor_sync(0xffffffffu, s0, 1);
            s0 += __shfl_xor_sync(0xffffffffu, s0, 2);
            s1 += __shfl_xor_sync(0xffffffffu, s1, 1);
            s1 += __shfl_xor_sync(0xffffffffu, s1, 2);
            l0 = l0 * a0 + s0;
            l1 = l1 * a1 + s1;

#pragma unroll
            for (int n = 0; n < 16; n++) {
                of[n][0] *= a0; of[n][1] *= a0;
                of[n][2] *= a1; of[n][3] *= a1;
            }

            // ---- O += P V : P fragments via quad shuffles, LDS.64 V ----
            const int base = lane & ~3;
            const int hsrc = base + (tg >> 1);
            const bool par = (tg & 1);
#pragma unroll
            for (int kc = 0; kc < 8; kc++) {
                uint32_t a[4];
                {
                    float lo = __shfl_sync(0xffffffffu, sacc[kc][0], hsrc);
                    float hi = __shfl_sync(0xffffffffu, sacc[kc][1], hsrc);
                    a[0] = __float_as_uint(par ? hi : lo);
                    lo = __shfl_sync(0xffffffffu, sacc[kc][2], hsrc);
                    hi = __shfl_sync(0xffffffffu, sacc[kc][3], hsrc);
                    a[1] = __float_as_uint(par ? hi : lo);
                    lo = __shfl_sync(0xffffffffu, sacc[kc][0], hsrc + 2);
                    hi = __shfl_sync(0xffffffffu, sacc[kc][1], hsrc + 2);
                    a[2] = __float_as_uint(par ? hi : lo);
                    lo = __shfl_sync(0xffffffffu, sacc[kc][2], hsrc + 2);
                    hi = __shfl_sync(0xffffffffu, sacc[kc][3], hsrc + 2);
                    a[3] = __float_as_uint(par ? hi : lo);
                }
#pragma unroll
                for (int n = 0; n < 16; n++) {
                    float2 vv = sV2[(kc * 16 + n) * 32 + vOff];
                    uint32_t bf[2] = { __float_as_uint(vv.x), __float_as_uint(vv.y) };
                    mma_tf32(of[n], a, bf);
                }
            }
        }
        __syncthreads();
    }

    // ---- epilogue ----
    const int b = bh >> 4, h = bh & 15;
    const float inv0 = 1.0f / l0;
    const float inv1 = 1.0f / l1;
    const int t0 = qt * 128 + wm + g;
    const int t1 = t0 + 8;
#pragma unroll
    for (int n = 0; n < 16; n++) {
        int d = 8 * n + 2 * tg;
        *(float2*)&Y[((size_t)(b * L_ + t0)) * H_ + h * HD_ + d] =
            make_float2(of[n][0] * inv0, of[n][1] * inv0);
        *(float2*)&Y[((size_t)(b * L_ + t1)) * H_ + h * HD_ + d] =
            make_float2(of[n][2] * inv1, of[n][3] * inv1);
    }
}

// ---------------- launcher ----------------------------------------------------
extern "C" void kernel_launch(void* const* d_in, const int* in_sizes, int n_in,
                              void* d_out, int out_size)
{
    const float* x    = (const float*)d_in[0];
    const float* Wqkv = (const float*)d_in[1];
    const float* bqkv = (const float*)d_in[2];
    const float* Wfc2 = (const float*)d_in[3];
    const float* bfc2 = (const float*)d_in[4];
    const float* cosb = (const float*)d_in[5];
    const float* sinb = (const float*)d_in[6];
    float* out = (float*)d_out;

    float *qkv, *Qh, *Kh, *Vh, *Yb;
    cudaGetSymbolAddress((void**)&qkv, g_qkv);
    cudaGetSymbolAddress((void**)&Qh,  g_Q);
    cudaGetSymbolAddress((void**)&Kh,  g_K);
    cudaGetSymbolAddress((void**)&Vh,  g_V);
    cudaGetSymbolAddress((void**)&Yb,  g_Y);

    cudaFuncSetAttribute(gemm_tf32, cudaFuncAttributeMaxDynamicSharedMemorySize, GEMM_SMEM);
    cudaFuncSetAttribute(attn_tc3, cudaFuncAttributeMaxDynamicSharedMemorySize, ATTN_SMEM);

    // 1) QKV GEMM
    gemm_tf32<<<dim3(N3_ / BN, M_ / BM), 256, GEMM_SMEM>>>(x, Wqkv, bqkv, qkv, M_, N3_, H_, 0);

    // 2) RoPE + scatter (Q row-major pre-scaled; K/V fragment-major)
    rope_scatter<<<M_, 256>>>(qkv, cosb, sinb, Qh, Kh, Vh);

    // 3) causal flash attention v3
    attn_tc3<<<dim3(L_ / 128, B_ * NH_), 256, ATTN_SMEM>>>(Qh, Kh, Vh, Yb);

    // 4) FC2 GEMM + SiLU
    gemm_tf32<<<dim3(H_ / BN, M_ / BM), 256, GEMM_SMEM>>>(Yb, Wfc2, bfc2, out, M_, H_, H_, 1);
}